// round 1
// baseline (speedup 1.0000x reference)
#include <cuda_runtime.h>

typedef unsigned long long ull;

#define DD    1024
#define LLEN  2048
#define KK    32
#define NSLOT 16
#define STEPS (LLEN / 32)

// ---- packed f32x2 helpers (Blackwell-only PTX; ptxas never emits these from C++) ----
__device__ __forceinline__ ull f2pack(float lo, float hi) {
    ull r;
    asm("mov.b64 %0, {%1, %2};" : "=l"(r) : "r"(__float_as_uint(lo)), "r"(__float_as_uint(hi)));
    return r;
}
__device__ __forceinline__ void f2unpack(ull v, float& lo, float& hi) {
    unsigned a, b;
    asm("mov.b64 {%0, %1}, %2;" : "=r"(a), "=r"(b) : "l"(v));
    lo = __uint_as_float(a);
    hi = __uint_as_float(b);
}
__device__ __forceinline__ ull f2add(ull a, ull b) {
    ull d; asm("add.rn.f32x2 %0, %1, %2;" : "=l"(d) : "l"(a), "l"(b)); return d;
}
__device__ __forceinline__ ull f2mul(ull a, ull b) {
    ull d; asm("mul.rn.f32x2 %0, %1, %2;" : "=l"(d) : "l"(a), "l"(b)); return d;
}
__device__ __forceinline__ ull f2fma(ull a, ull b, ull c) {
    ull d; asm("fma.rn.f32x2 %0, %1, %2, %3;" : "=l"(d) : "l"(a), "l"(b), "l"(c)); return d;
}

// One warp per output row d. Lane j at step i produces l = 32*i + j:
//   h[d][l] = Re( sum_k w_k ),  w_k = R_k * p_k^(l-1),  step: w_k *= q_k = p_k^32.
// q is warp-uniform (same d across lanes) so stores are fully coalesced.
__global__ void __launch_bounds__(128) modal_kernel(
    const float* __restrict__ rr, const float* __restrict__ th,
    const float* __restrict__ Rre, const float* __restrict__ Rim,
    const float* __restrict__ h0, float* __restrict__ out)
{
    const int lane = threadIdx.x & 31;
    const int d = blockIdx.x * 4 + (threadIdx.x >> 5);

    const float INV2PI = 0.15915494309189535f;
    const float PI2_HI = 6.2831854820251465f;    // fp32(2*pi)
    const float PI2_LO = -1.7484555e-7f;         // 2*pi - PI2_HI

    ull wre[NSLOT], wim[NSLOT], qre[NSLOT], qim[NSLOT], mqim[NSLOT];

    const float e0 = (float)(lane - 1);          // exponent at step 0 (l = lane)
    float p_wre = 0.f, p_wim = 0.f, p_qre = 0.f, p_qim = 0.f;

#pragma unroll
    for (int k = 0; k < KK; ++k) {
        const int off = k * DD + d;              // warp-uniform address -> broadcast load
        float rk = __ldg(rr + off);
        float tk = __ldg(th + off);
        float ar = __ldg(Rre + off);
        float ai = __ldg(Rim + off);
        float lr = __logf(rk);

        // w_k = R_k * p_k^e0    (|e0| <= 30, angle <= ~190 rad before reduction)
        float rad = __expf(e0 * lr);
        float ang = e0 * tk;
        float n = rintf(ang * INV2PI);
        ang = fmaf(-n, PI2_HI, ang);
        ang = fmaf(-n, PI2_LO, ang);
        float s, c;
        __sincosf(ang, &s, &c);
        float cwre = rad * (ar * c - ai * s);
        float cwim = rad * (ar * s + ai * c);

        // q_k = p_k^32   (32*theta exact in fp32; n <= 32)
        float qrad = __expf(32.0f * lr);
        float qa = 32.0f * tk;
        float nq = rintf(qa * INV2PI);
        qa = fmaf(-nq, PI2_HI, qa);
        qa = fmaf(-nq, PI2_LO, qa);
        float qs, qc;
        __sincosf(qa, &qs, &qc);
        float cqre = qrad * qc;
        float cqim = qrad * qs;

        if (k & 1) {
            wre [k >> 1] = f2pack(p_wre, cwre);
            wim [k >> 1] = f2pack(p_wim, cwim);
            qre [k >> 1] = f2pack(p_qre, cqre);
            qim [k >> 1] = f2pack(p_qim, cqim);
            mqim[k >> 1] = f2pack(-p_qim, -cqim);
        } else {
            p_wre = cwre; p_wim = cwim; p_qre = cqre; p_qim = cqim;
        }
    }

    const float h00 = __ldg(h0 + d);
    float* outp = out + (size_t)d * LLEN + lane;

#pragma unroll 1
    for (int i = 0; i < STEPS; ++i) {
        // horizontal sum of Re(w) over 16 packed slots (binary tree: 15 packed adds)
        ull a0 = f2add(wre[0],  wre[1]);
        ull a1 = f2add(wre[2],  wre[3]);
        ull a2 = f2add(wre[4],  wre[5]);
        ull a3 = f2add(wre[6],  wre[7]);
        ull a4 = f2add(wre[8],  wre[9]);
        ull a5 = f2add(wre[10], wre[11]);
        ull a6 = f2add(wre[12], wre[13]);
        ull a7 = f2add(wre[14], wre[15]);
        ull b0 = f2add(a0, a1);
        ull b1 = f2add(a2, a3);
        ull b2 = f2add(a4, a5);
        ull b3 = f2add(a6, a7);
        ull c0 = f2add(b0, b1);
        ull c1 = f2add(b2, b3);
        ull t  = f2add(c0, c1);
        float lo, hi;
        f2unpack(t, lo, hi);
        float h = lo + hi;
        if ((i | lane) == 0) h = h00;            // l==0 row is h_0
        outp[i * 32] = h;                        // coalesced 128B store per warp

        // w *= q  (16 independent packed complex-multiply chains -> 16-way ILP)
#pragma unroll
        for (int s2 = 0; s2 < NSLOT; ++s2) {
            ull t1 = f2mul(wre[s2], qre[s2]);
            ull nr = f2fma(wim[s2], mqim[s2], t1);
            ull t2 = f2mul(wre[s2], qim[s2]);
            ull ni = f2fma(wim[s2], qre[s2], t2);
            wre[s2] = nr;
            wim[s2] = ni;
        }
    }
}

extern "C" void kernel_launch(void* const* d_in, const int* in_sizes, int n_in,
                              void* d_out, int out_size) {
    const float* rr  = (const float*)d_in[0];
    const float* th  = (const float*)d_in[1];
    const float* Rre = (const float*)d_in[2];
    const float* Rim = (const float*)d_in[3];
    const float* h0  = (const float*)d_in[4];
    float* out = (float*)d_out;
    modal_kernel<<<DD / 4, 128>>>(rr, th, Rre, Rim, h0, out);
}

// round 2
// speedup vs baseline: 1.0094x; 1.0094x over previous
#include <cuda_runtime.h>

typedef unsigned long long ull;

#define DD    1024
#define LLEN  2048
#define KK    32
#define NSLOT 16
#define STEPS (LLEN / 32)

// ---- packed f32x2 helpers (Blackwell-only PTX; ptxas never emits these from C++) ----
__device__ __forceinline__ ull f2pack(float lo, float hi) {
    ull r;
    asm("mov.b64 %0, {%1, %2};" : "=l"(r) : "r"(__float_as_uint(lo)), "r"(__float_as_uint(hi)));
    return r;
}
__device__ __forceinline__ void f2unpack(ull v, float& lo, float& hi) {
    unsigned a, b;
    asm("mov.b64 {%0, %1}, %2;" : "=r"(a), "=r"(b) : "l"(v));
    lo = __uint_as_float(a);
    hi = __uint_as_float(b);
}
__device__ __forceinline__ ull f2add(ull a, ull b) {
    ull d; asm("add.rn.f32x2 %0, %1, %2;" : "=l"(d) : "l"(a), "l"(b)); return d;
}
__device__ __forceinline__ ull f2mul(ull a, ull b) {
    ull d; asm("mul.rn.f32x2 %0, %1, %2;" : "=l"(d) : "l"(a), "l"(b)); return d;
}
__device__ __forceinline__ ull f2fma(ull a, ull b, ull c) {
    ull d; asm("fma.rn.f32x2 %0, %1, %2, %3;" : "=l"(d) : "l"(a), "l"(b), "l"(c)); return d;
}

// One warp per output row d. Lane j at step i produces l = 32*i + j:
//   h[d][l] = Re( sum_k w_k ),  w_k = R_k * p_k^(l-1),  step: w_k *= q_k = p_k^32.
// q is warp-uniform (same d across lanes) so stores are fully coalesced.
__global__ void __launch_bounds__(128) modal_kernel(
    const float* __restrict__ rr, const float* __restrict__ th,
    const float* __restrict__ Rre, const float* __restrict__ Rim,
    const float* __restrict__ h0, float* __restrict__ out)
{
    const int lane = threadIdx.x & 31;
    const int d = blockIdx.x * 4 + (threadIdx.x >> 5);

    const float INV2PI = 0.15915494309189535f;
    const float PI2_HI = 6.2831854820251465f;    // fp32(2*pi)
    const float PI2_LO = -1.7484555e-7f;         // 2*pi - PI2_HI

    ull wre[NSLOT], wim[NSLOT], qre[NSLOT], qim[NSLOT], mqim[NSLOT];

    const float e0 = (float)(lane - 1);          // exponent at step 0 (l = lane)
    float p_wre = 0.f, p_wim = 0.f, p_qre = 0.f, p_qim = 0.f;

#pragma unroll
    for (int k = 0; k < KK; ++k) {
        const int off = k * DD + d;              // warp-uniform address -> broadcast load
        float rk = __ldg(rr + off);
        float tk = __ldg(th + off);
        float ar = __ldg(Rre + off);
        float ai = __ldg(Rim + off);
        float lr = __logf(rk);

        // w_k = R_k * p_k^e0    (|e0| <= 30, angle <= ~190 rad before reduction)
        float rad = __expf(e0 * lr);
        float ang = e0 * tk;
        float n = rintf(ang * INV2PI);
        ang = fmaf(-n, PI2_HI, ang);
        ang = fmaf(-n, PI2_LO, ang);
        float s, c;
        __sincosf(ang, &s, &c);
        float cwre = rad * (ar * c - ai * s);
        float cwim = rad * (ar * s + ai * c);

        // q_k = p_k^32   (32*theta exact in fp32; n <= 32)
        float qrad = __expf(32.0f * lr);
        float qa = 32.0f * tk;
        float nq = rintf(qa * INV2PI);
        qa = fmaf(-nq, PI2_HI, qa);
        qa = fmaf(-nq, PI2_LO, qa);
        float qs, qc;
        __sincosf(qa, &qs, &qc);
        float cqre = qrad * qc;
        float cqim = qrad * qs;

        if (k & 1) {
            wre [k >> 1] = f2pack(p_wre, cwre);
            wim [k >> 1] = f2pack(p_wim, cwim);
            qre [k >> 1] = f2pack(p_qre, cqre);
            qim [k >> 1] = f2pack(p_qim, cqim);
            mqim[k >> 1] = f2pack(-p_qim, -cqim);
        } else {
            p_wre = cwre; p_wim = cwim; p_qre = cqre; p_qim = cqim;
        }
    }

    const float h00 = __ldg(h0 + d);
    float* outp = out + (size_t)d * LLEN + lane;

#pragma unroll 1
    for (int i = 0; i < STEPS; ++i) {
        // horizontal sum of Re(w) over 16 packed slots (binary tree: 15 packed adds)
        ull a0 = f2add(wre[0],  wre[1]);
        ull a1 = f2add(wre[2],  wre[3]);
        ull a2 = f2add(wre[4],  wre[5]);
        ull a3 = f2add(wre[6],  wre[7]);
        ull a4 = f2add(wre[8],  wre[9]);
        ull a5 = f2add(wre[10], wre[11]);
        ull a6 = f2add(wre[12], wre[13]);
        ull a7 = f2add(wre[14], wre[15]);
        ull b0 = f2add(a0, a1);
        ull b1 = f2add(a2, a3);
        ull b2 = f2add(a4, a5);
        ull b3 = f2add(a6, a7);
        ull c0 = f2add(b0, b1);
        ull c1 = f2add(b2, b3);
        ull t  = f2add(c0, c1);
        float lo, hi;
        f2unpack(t, lo, hi);
        float h = lo + hi;
        if ((i | lane) == 0) h = h00;            // l==0 row is h_0
        outp[i * 32] = h;                        // coalesced 128B store per warp

        // w *= q  (16 independent packed complex-multiply chains -> 16-way ILP)
#pragma unroll
        for (int s2 = 0; s2 < NSLOT; ++s2) {
            ull t1 = f2mul(wre[s2], qre[s2]);
            ull nr = f2fma(wim[s2], mqim[s2], t1);
            ull t2 = f2mul(wre[s2], qim[s2]);
            ull ni = f2fma(wim[s2], qre[s2], t2);
            wre[s2] = nr;
            wim[s2] = ni;
        }
    }
}

extern "C" void kernel_launch(void* const* d_in, const int* in_sizes, int n_in,
                              void* d_out, int out_size) {
    const float* rr  = (const float*)d_in[0];
    const float* th  = (const float*)d_in[1];
    const float* Rre = (const float*)d_in[2];
    const float* Rim = (const float*)d_in[3];
    const float* h0  = (const float*)d_in[4];
    float* out = (float*)d_out;
    modal_kernel<<<DD / 4, 128>>>(rr, th, Rre, Rim, h0, out);
}